// round 12
// baseline (speedup 1.0000x reference)
#include <cuda_runtime.h>
#include <cuda_bf16.h>
#include <math.h>
#include <stdint.h>

#define VSZ 50000
#define ESZ 256
#define HSZ 512
#define BSZ 128
#define LSZ 400
#define TSZ 100
#define K3H 1536

// ---------------- scratch (device globals; no allocation allowed) ----------------
__device__ float g_te[BSZ * HSZ];
__device__ float g_td[BSZ * HSZ];
__device__ float g_alpha[BSZ * LSZ];
__device__ float g_nh[BSZ * K3H];     // [c_t_e | h | c_t_d]
__device__ float g_p[BSZ];            // pointer_prob

__device__ __forceinline__ float warp_sum(float v) {
    #pragma unroll
    for (int o = 16; o > 0; o >>= 1) v += __shfl_down_sync(0xffffffffu, v, o);
    return v;
}

// ---------------- K1: embed + GRU + te/td (2 batch rows per block) ----------------
__global__ void __launch_bounds__(256) k_gru(
    const int* __restrict__ inputs,
    const float* __restrict__ hidden,
    const float* __restrict__ emb,
    const float* __restrict__ W_ih,
    const float* __restrict__ W_hh,
    const float* __restrict__ b_ih, const float* __restrict__ b_hh,
    const float* __restrict__ W_ae, const float* __restrict__ b_ae,
    const float* __restrict__ W_ad, const float* __restrict__ b_ad,
    float* __restrict__ h_out)
{
    __shared__ float sx[2][ESZ];
    __shared__ float sh[2][HSZ];
    __shared__ float sgi[2][K3H];
    __shared__ float sgh[2][K3H];
    __shared__ float shn[2][HSZ];

    const int b0 = blockIdx.x * 2;
    const int t = threadIdx.x;
    const int w = t >> 5, lane = t & 31;

    sx[0][t] = emb[(size_t)inputs[b0] * ESZ + t];
    sx[1][t] = emb[(size_t)inputs[b0 + 1] * ESZ + t];
    #pragma unroll
    for (int i = t; i < 2 * HSZ; i += 256) {
        int u = i >> 9, hh = i & (HSZ - 1);
        sh[u][hh] = hidden[(b0 + u) * HSZ + hh];
    }
    __syncthreads();

    for (int j = w; j < K3H; j += 8) {
        const float* wi = W_ih + (size_t)j * ESZ;
        const float* wh = W_hh + (size_t)j * HSZ;
        float si0 = 0.f, si1 = 0.f, sg0 = 0.f, sg1 = 0.f;
        #pragma unroll
        for (int i = lane; i < ESZ; i += 32) {
            float wv = wi[i];
            si0 += wv * sx[0][i]; si1 += wv * sx[1][i];
        }
        #pragma unroll
        for (int i = lane; i < HSZ; i += 32) {
            float wv = wh[i];
            sg0 += wv * sh[0][i]; sg1 += wv * sh[1][i];
        }
        si0 = warp_sum(si0); si1 = warp_sum(si1);
        sg0 = warp_sum(sg0); sg1 = warp_sum(sg1);
        if (lane == 0) {
            float bi = b_ih[j], bh = b_hh[j];
            sgi[0][j] = si0 + bi; sgi[1][j] = si1 + bi;
            sgh[0][j] = sg0 + bh; sgh[1][j] = sg1 + bh;
        }
    }
    __syncthreads();

    #pragma unroll
    for (int i = t; i < 2 * HSZ; i += 256) {
        int u = i >> 9, hh = i & (HSZ - 1);
        float r = 1.f / (1.f + expf(-(sgi[u][hh] + sgh[u][hh])));
        float z = 1.f / (1.f + expf(-(sgi[u][hh + HSZ] + sgh[u][hh + HSZ])));
        float n = tanhf(sgi[u][hh + 2 * HSZ] + r * sgh[u][hh + 2 * HSZ]);
        float hn = (1.f - z) * n + z * sh[u][hh];
        shn[u][hh] = hn;
        h_out[(b0 + u) * HSZ + hh] = hn;
        g_nh[(b0 + u) * K3H + HSZ + hh] = hn;
    }
    __syncthreads();

    for (int j = w; j < HSZ; j += 8) {
        const float* wa = W_ae + (size_t)j * HSZ;
        const float* wd = W_ad + (size_t)j * HSZ;
        float a0 = 0.f, a1 = 0.f, d0 = 0.f, d1 = 0.f;
        #pragma unroll
        for (int i = lane; i < HSZ; i += 32) {
            float av = wa[i], dv = wd[i];
            a0 += av * shn[0][i]; a1 += av * shn[1][i];
            d0 += dv * shn[0][i]; d1 += dv * shn[1][i];
        }
        a0 = warp_sum(a0); a1 = warp_sum(a1);
        d0 = warp_sum(d0); d1 = warp_sum(d1);
        if (lane == 0) {
            float ba = b_ae[j], bd = b_ad[j];
            g_te[b0 * HSZ + j] = a0 + ba; g_te[(b0 + 1) * HSZ + j] = a1 + ba;
            g_td[b0 * HSZ + j] = d0 + bd; g_td[(b0 + 1) * HSZ + j] = d1 + bd;
        }
    }
}

// ---------------- K2: attention -----------------------------------------------
template<int S, int NHOFF, bool USE_TD, bool MASK, bool STORE_ALPHA>
__global__ void __launch_bounds__(512) k_attn(
    const float* __restrict__ kv,
    const int* __restrict__ lengths)
{
    __shared__ float sq[HSZ];
    __shared__ float sc[S];
    __shared__ float sred[512];

    const int b = blockIdx.x;
    const int t = threadIdx.x;
    const int w = t >> 5, lane = t & 31;

    const float* q = USE_TD ? g_td : g_te;
    sq[t] = q[b * HSZ + t];
    __syncthreads();

    int len = MASK ? lengths[b] : S;

    for (int l = w; l < S; l += 16) {
        const float* row = kv + ((size_t)l * BSZ + b) * HSZ;
        float s = 0.f;
        #pragma unroll 4
        for (int i = lane; i < HSZ; i += 32) s += row[i] * sq[i];
        s = warp_sum(s);
        if (lane == 0) {
            if (MASK && (S < len) && (l >= len)) s = -INFINITY;
            sc[l] = s;
        }
    }
    __syncthreads();

    float v = (t < S) ? sc[t] : -INFINITY;
    sred[t] = v; __syncthreads();
    #pragma unroll
    for (int o = 256; o > 0; o >>= 1) { if (t < o) sred[t] = fmaxf(sred[t], sred[t + o]); __syncthreads(); }
    float m = sred[0]; __syncthreads();
    float e = (t < S) ? expf(sc[t] - m) : 0.f;
    sred[t] = e; __syncthreads();
    #pragma unroll
    for (int o = 256; o > 0; o >>= 1) { if (t < o) sred[t] += sred[t + o]; __syncthreads(); }
    float ssum = sred[0]; __syncthreads();
    if (t < S) {
        float a = e / ssum;
        sc[t] = a;
        if (STORE_ALPHA) g_alpha[b * S + t] = a;
    }
    __syncthreads();

    float c = 0.f;
    const float* base = kv + (size_t)b * HSZ + t;
    #pragma unroll 4
    for (int l = 0; l < S; l++) c += sc[l] * base[(size_t)l * BSZ * HSZ];
    g_nh[b * K3H + NHOFF + t] = c;
}

// ---------------- K3: pointer prob (block per b) --------------------------------
__global__ void __launch_bounds__(256) k_pointer(
    const float* __restrict__ W_ptr, const float* __restrict__ b_ptr)
{
    __shared__ float sred[8];
    const int b = blockIdx.x;
    const int t = threadIdx.x;
    const int w = t >> 5, lane = t & 31;
    float s = 0.f;
    #pragma unroll
    for (int i = t; i < K3H; i += 256) s += g_nh[b * K3H + i] * W_ptr[i];
    s = warp_sum(s);
    if (lane == 0) sred[w] = s;
    __syncthreads();
    if (t == 0) {
        float tot = 0.f;
        #pragma unroll
        for (int i = 0; i < 8; i++) tot += sred[i];
        g_p[b] = tot + b_ptr[0];
    }
}

// ---------------- K4: bf16 mma.sync GEMM: logits = nh @ W^T + bias --------------
// Block 128(M) x 128(N) x 32(K). 8 warps (2m x 4n), warp tile 64x32.
// Prefetch distance 2: sts at iter top (buffer whose readers retired at the
// previous sync), ldg(t+2) issued immediately after, consumed next iter.
#define GBN 128
#define GBK 32
#define NKT (K3H / GBK)     // 48
#define AST 20              // row stride in words; frag LDS pattern covers all 32 banks
#define TBUF (BSZ * AST)

__device__ __forceinline__ void mma_bf16(float* d, const uint32_t* a, const uint32_t* b) {
    asm volatile(
        "mma.sync.aligned.m16n8k16.row.col.f32.bf16.bf16.f32 "
        "{%0,%1,%2,%3}, {%4,%5,%6,%7}, {%8,%9}, {%0,%1,%2,%3};\n"
        : "+f"(d[0]), "+f"(d[1]), "+f"(d[2]), "+f"(d[3])
        : "r"(a[0]), "r"(a[1]), "r"(a[2]), "r"(a[3]), "r"(b[0]), "r"(b[1]));
}

__global__ void __launch_bounds__(256, 2) k_gemm_bf16(
    const float* __restrict__ W,        // (V, K3H)
    const float* __restrict__ bias,     // (V,)
    float* __restrict__ out)            // (B, V)
{
    __shared__ uint32_t sa[2][TBUF];
    __shared__ uint32_t sb[2][TBUF];

    const int tid  = threadIdx.x;
    const int warp = tid >> 5, lane = tid & 31;
    const int g    = lane >> 2, tig = lane & 3;
    const int wm   = (warp >> 2) * 64;
    const int wn   = (warp & 3) * 32;
    const int n0   = blockIdx.x * GBN;

    const int srow = tid >> 1;
    const int shalf = (tid & 1);
    const bool bvalid = (n0 + srow) < VSZ;
    const float* aptr = g_nh + (size_t)srow * K3H + shalf * 16;
    const float* bptr = W + (size_t)(n0 + srow) * K3H + shalf * 16;

    uint32_t pa[8], pb[8];

    auto ldg_pack = [&](int kt) {
        const float4* a4 = (const float4*)(aptr + kt * GBK);
        #pragma unroll
        for (int q = 0; q < 4; q++) {
            float4 v = a4[q];
            __nv_bfloat162 lo = __floats2bfloat162_rn(v.x, v.y);
            __nv_bfloat162 hi = __floats2bfloat162_rn(v.z, v.w);
            pa[2 * q]     = *(uint32_t*)&lo;
            pa[2 * q + 1] = *(uint32_t*)&hi;
        }
        if (bvalid) {
            const float4* b4 = (const float4*)(bptr + kt * GBK);
            #pragma unroll
            for (int q = 0; q < 4; q++) {
                float4 v = b4[q];
                __nv_bfloat162 lo = __floats2bfloat162_rn(v.x, v.y);
                __nv_bfloat162 hi = __floats2bfloat162_rn(v.z, v.w);
                pb[2 * q]     = *(uint32_t*)&lo;
                pb[2 * q + 1] = *(uint32_t*)&hi;
            }
        } else {
            #pragma unroll
            for (int q = 0; q < 8; q++) pb[q] = 0u;
        }
    };
    auto sts = [&](int buf) {
        uint32_t* A = &sa[buf][srow * AST + shalf * 8];
        uint32_t* B = &sb[buf][srow * AST + shalf * 8];
        *(uint4*)(A)     = make_uint4(pa[0], pa[1], pa[2], pa[3]);
        *(uint4*)(A + 4) = make_uint4(pa[4], pa[5], pa[6], pa[7]);
        *(uint4*)(B)     = make_uint4(pb[0], pb[1], pb[2], pb[3]);
        *(uint4*)(B + 4) = make_uint4(pb[4], pb[5], pb[6], pb[7]);
    };

    float acc[4][4][4];
    #pragma unroll
    for (int mi = 0; mi < 4; mi++)
        #pragma unroll
        for (int nf = 0; nf < 4; nf++)
            #pragma unroll
            for (int r = 0; r < 4; r++) acc[mi][nf][r] = 0.f;

    ldg_pack(0);
    sts(0);
    ldg_pack(1);
    __syncthreads();

    for (int t = 0; t < NKT; t++) {
        const int cur = t & 1;
        if (t + 1 < NKT) sts((t + 1) & 1);   // regs from ldg(t+1); buffer's readers retired
        if (t + 2 < NKT) ldg_pack(t + 2);    // in flight across mma + sync

        #pragma unroll
        for (int kh = 0; kh < 2; kh++) {
            const int kb = kh * 8 + tig;
            uint32_t bf[4][2];
            #pragma unroll
            for (int nf = 0; nf < 4; nf++) {
                const int r = wn + nf * 8 + g;
                bf[nf][0] = sb[cur][r * AST + kb];
                bf[nf][1] = sb[cur][r * AST + kb + 4];
            }
            #pragma unroll
            for (int mi = 0; mi < 4; mi++) {
                const int r0 = wm + mi * 16 + g;
                uint32_t af[4];
                af[0] = sa[cur][r0 * AST + kb];
                af[1] = sa[cur][(r0 + 8) * AST + kb];
                af[2] = sa[cur][r0 * AST + kb + 4];
                af[3] = sa[cur][(r0 + 8) * AST + kb + 4];
                #pragma unroll
                for (int nf = 0; nf < 4; nf++) mma_bf16(acc[mi][nf], af, bf[nf]);
            }
        }
        __syncthreads();
    }

    #pragma unroll
    for (int mi = 0; mi < 4; mi++) {
        const int m = wm + mi * 16 + g;
        #pragma unroll
        for (int nf = 0; nf < 4; nf++) {
            const int gn = n0 + wn + nf * 8 + 2 * tig;
            if (gn < VSZ) {
                float2 bv = *(const float2*)(bias + gn);
                float2 o0 = { acc[mi][nf][0] + bv.x, acc[mi][nf][1] + bv.y };
                float2 o1 = { acc[mi][nf][2] + bv.x, acc[mi][nf][3] + bv.y };
                *(float2*)(out + (size_t)m * VSZ + gn) = o0;
                *(float2*)(out + (size_t)(m + 8) * VSZ + gn) = o1;
            }
        }
    }
}

// ---------------- K5: fused logsumexp + finalize (block per row) -----------------
__global__ void __launch_bounds__(1024) k_lsefin(float* __restrict__ out)
{
    __shared__ float sr[1024];
    const int b = blockIdx.x, t = threadIdx.x;
    float* row = out + (size_t)b * VSZ;

    float m = -INFINITY;
    for (int i = t; i < VSZ; i += 1024) m = fmaxf(m, row[i]);
    sr[t] = m; __syncthreads();
    #pragma unroll
    for (int o = 512; o > 0; o >>= 1) { if (t < o) sr[t] = fmaxf(sr[t], sr[t + o]); __syncthreads(); }
    m = sr[0]; __syncthreads();

    float s = 0.f;
    for (int i = t; i < VSZ; i += 1024) s += expf(row[i] - m);
    sr[t] = s; __syncthreads();
    #pragma unroll
    for (int o = 512; o > 0; o >>= 1) { if (t < o) sr[t] += sr[t + o]; __syncthreads(); }
    float lse = m + logf(sr[0]);
    float scale = 1.f - g_p[b];
    __syncthreads();

    for (int i = t; i < VSZ; i += 1024) row[i] = scale * (row[i] - lse);
}

// ---------------- K6: pointer scatter add --------------------------------------
__global__ void __launch_bounds__(256) k_scatter(
    float* __restrict__ out, const int* __restrict__ enc_inputs)
{
    int i = blockIdx.x * blockDim.x + threadIdx.x;
    if (i >= BSZ * LSZ) return;
    int b = i & (BSZ - 1);
    int l = i >> 7;
    int tok = enc_inputs[l * BSZ + b];
    atomicAdd(out + (size_t)b * VSZ + tok, g_p[b] * g_alpha[b * LSZ + l]);
}

// ---------------- launch --------------------------------------------------------
extern "C" void kernel_launch(void* const* d_in, const int* in_sizes, int n_in,
                              void* d_out, int out_size)
{
    const int*   inputs      = (const int*)  d_in[0];
    const float* hidden      = (const float*)d_in[1];
    const float* enc_hidden  = (const float*)d_in[2];
    const int*   enc_lengths = (const int*)  d_in[3];
    const float* prev_w      = (const float*)d_in[4];
    const float* dec_hidden  = (const float*)d_in[5];
    const int*   enc_inputs  = (const int*)  d_in[6];

    int wbase = 7;
    for (int i = 7; i < n_in; i++) {
        if (in_sizes[i] == VSZ * ESZ) { wbase = i; break; }
    }
    const float* emb   = (const float*)d_in[wbase + 0];
    const float* W_ih  = (const float*)d_in[wbase + 1];
    const float* W_hh  = (const float*)d_in[wbase + 2];
    const float* b_ih  = (const float*)d_in[wbase + 3];
    const float* b_hh  = (const float*)d_in[wbase + 4];
    const float* W_ae  = (const float*)d_in[wbase + 5];
    const float* b_ae  = (const float*)d_in[wbase + 6];
    const float* W_ad  = (const float*)d_in[wbase + 7];
    const float* b_ad  = (const float*)d_in[wbase + 8];
    const float* W_ptr = (const float*)d_in[wbase + 9];
    const float* b_ptr = (const float*)d_in[wbase + 10];
    const float* W_out = (const float*)d_in[wbase + 11];
    const float* b_out = (const float*)d_in[wbase + 12];

    float* out     = (float*)d_out;
    float* h_out   = out + (size_t)BSZ * VSZ;
    float* pw_out  = h_out + (size_t)BSZ * HSZ;

    k_gru<<<BSZ / 2, 256>>>(inputs, hidden, emb, W_ih, W_hh, b_ih, b_hh,
                            W_ae, b_ae, W_ad, b_ad, h_out);

    k_attn<LSZ, 0,       false, true,  true ><<<BSZ, 512>>>(enc_hidden, enc_lengths);
    k_attn<TSZ, 2 * HSZ, true,  false, false><<<BSZ, 512>>>(dec_hidden, enc_lengths);

    // GEMM in launch slot 3 — the slot ncu has captured every round.
    k_gemm_bf16<<<(VSZ + GBN - 1) / GBN, 256>>>(W_out, b_out, out);

    k_pointer<<<BSZ, 256>>>(W_ptr, b_ptr);

    k_lsefin<<<BSZ, 1024>>>(out);

    k_scatter<<<(BSZ * LSZ + 255) / 256, 256>>>(out, enc_inputs);

    cudaMemcpyAsync(pw_out, prev_w, (size_t)BSZ * LSZ * sizeof(float),
                    cudaMemcpyDeviceToDevice, 0);
}

// round 14
// speedup vs baseline: 1.3469x; 1.3469x over previous
#include <cuda_runtime.h>
#include <cuda_bf16.h>
#include <math.h>
#include <stdint.h>

#define VSZ 50000
#define ESZ 256
#define HSZ 512
#define BSZ 128
#define LSZ 400
#define TSZ 100
#define K3H 1536

// ---------------- scratch (device globals; no allocation allowed) ----------------
__device__ float g_te[BSZ * HSZ];
__device__ float g_td[BSZ * HSZ];
__device__ float g_alpha[BSZ * LSZ];
__device__ float g_nh[BSZ * K3H];     // [c_t_e | h | c_t_d]
__device__ float g_p[BSZ];            // pointer_prob

__device__ __forceinline__ float warp_sum(float v) {
    #pragma unroll
    for (int o = 16; o > 0; o >>= 1) v += __shfl_down_sync(0xffffffffu, v, o);
    return v;
}
__device__ __forceinline__ float dot4(float4 a, float4 b) {
    return a.x * b.x + a.y * b.y + a.z * b.z + a.w * b.w;
}

// ---------------- K0: embed + GRU gates (2 batch rows per block) ------------------
__global__ void __launch_bounds__(256) k_gru_gates(
    const int* __restrict__ inputs,
    const float* __restrict__ hidden,
    const float* __restrict__ emb,
    const float* __restrict__ W_ih,
    const float* __restrict__ W_hh,
    const float* __restrict__ b_ih, const float* __restrict__ b_hh,
    float* __restrict__ h_out)
{
    __shared__ float4 sx4[2][64];     // 2 x 256 floats
    __shared__ float4 sh4[2][128];    // 2 x 512 floats
    __shared__ float sgi[2][K3H];
    __shared__ float sgh[2][K3H];

    const int b0 = blockIdx.x * 2;
    const int t = threadIdx.x;
    const int w = t >> 5, lane = t & 31;

    if (t < 128) {
        int u = t >> 6, q = t & 63;
        sx4[u][q] = ((const float4*)(emb + (size_t)inputs[b0 + u] * ESZ))[q];
    }
    {
        int u = t >> 7, q = t & 127;
        sh4[u][q] = ((const float4*)(hidden + (size_t)(b0 + u) * HSZ))[q];
    }
    __syncthreads();

    for (int j = w; j < K3H; j += 8) {
        const float4* wi4 = (const float4*)(W_ih + (size_t)j * ESZ);
        const float4* wh4 = (const float4*)(W_hh + (size_t)j * HSZ);
        float si0 = 0.f, si1 = 0.f, sg0 = 0.f, sg1 = 0.f;
        #pragma unroll
        for (int q = 0; q < 2; q++) {
            float4 wv = wi4[lane + 32 * q];
            si0 += dot4(wv, sx4[0][lane + 32 * q]);
            si1 += dot4(wv, sx4[1][lane + 32 * q]);
        }
        #pragma unroll
        for (int q = 0; q < 4; q++) {
            float4 wv = wh4[lane + 32 * q];
            sg0 += dot4(wv, sh4[0][lane + 32 * q]);
            sg1 += dot4(wv, sh4[1][lane + 32 * q]);
        }
        si0 = warp_sum(si0); si1 = warp_sum(si1);
        sg0 = warp_sum(sg0); sg1 = warp_sum(sg1);
        if (lane == 0) {
            float bi = b_ih[j], bh = b_hh[j];
            sgi[0][j] = si0 + bi; sgi[1][j] = si1 + bi;
            sgh[0][j] = sg0 + bh; sgh[1][j] = sg1 + bh;
        }
    }
    __syncthreads();

    const float* shf = (const float*)sh4;         // [u*512 + hh]
    #pragma unroll
    for (int i = t; i < 2 * HSZ; i += 256) {
        int u = i >> 9, hh = i & (HSZ - 1);
        float r = 1.f / (1.f + expf(-(sgi[u][hh] + sgh[u][hh])));
        float z = 1.f / (1.f + expf(-(sgi[u][hh + HSZ] + sgh[u][hh + HSZ])));
        float n = tanhf(sgi[u][hh + 2 * HSZ] + r * sgh[u][hh + 2 * HSZ]);
        float hn = (1.f - z) * n + z * shf[u * HSZ + hh];
        h_out[(b0 + u) * HSZ + hh] = hn;
        g_nh[(b0 + u) * K3H + HSZ + hh] = hn;
    }
}

// ---------------- K1: te/td projections (2 batch rows per block) -----------------
__global__ void __launch_bounds__(256) k_proj(
    const float* __restrict__ h_in,
    const float* __restrict__ W_ae, const float* __restrict__ b_ae,
    const float* __restrict__ W_ad, const float* __restrict__ b_ad)
{
    __shared__ float4 sh4[2][128];

    const int b0 = blockIdx.x * 2;
    const int t = threadIdx.x;
    const int w = t >> 5, lane = t & 31;

    {
        int u = t >> 7, q = t & 127;
        sh4[u][q] = ((const float4*)(h_in + (size_t)(b0 + u) * HSZ))[q];
    }
    __syncthreads();

    for (int j = w; j < HSZ; j += 8) {
        const float4* wa4 = (const float4*)(W_ae + (size_t)j * HSZ);
        const float4* wd4 = (const float4*)(W_ad + (size_t)j * HSZ);
        float a0 = 0.f, a1 = 0.f, d0 = 0.f, d1 = 0.f;
        #pragma unroll
        for (int q = 0; q < 4; q++) {
            float4 h0 = sh4[0][lane + 32 * q];
            float4 h1 = sh4[1][lane + 32 * q];
            float4 av = wa4[lane + 32 * q];
            float4 dv = wd4[lane + 32 * q];
            a0 += dot4(av, h0); a1 += dot4(av, h1);
            d0 += dot4(dv, h0); d1 += dot4(dv, h1);
        }
        a0 = warp_sum(a0); a1 = warp_sum(a1);
        d0 = warp_sum(d0); d1 = warp_sum(d1);
        if (lane == 0) {
            float ba = b_ae[j], bd = b_ad[j];
            g_te[b0 * HSZ + j] = a0 + ba; g_te[(b0 + 1) * HSZ + j] = a1 + ba;
            g_td[b0 * HSZ + j] = d0 + bd; g_td[(b0 + 1) * HSZ + j] = d1 + bd;
        }
    }
}

// ---------------- K2: attention (float4 scores, unroll-8 context) ----------------
template<int S, int NHOFF, bool USE_TD, bool MASK, bool STORE_ALPHA>
__global__ void __launch_bounds__(512) k_attn(
    const float* __restrict__ kv,
    const int* __restrict__ lengths)
{
    __shared__ float4 sq4[128];
    __shared__ float sc[S];
    __shared__ float sred[512];

    const int b = blockIdx.x;
    const int t = threadIdx.x;
    const int w = t >> 5, lane = t & 31;

    const float* q = USE_TD ? g_td : g_te;
    if (t < 128) sq4[t] = ((const float4*)(q + (size_t)b * HSZ))[t];
    __syncthreads();

    int len = MASK ? lengths[b] : S;

    for (int l = w; l < S; l += 16) {
        const float4* row4 = (const float4*)(kv + ((size_t)l * BSZ + b) * HSZ);
        float s = 0.f;
        #pragma unroll
        for (int qq = 0; qq < 4; qq++)
            s += dot4(row4[lane + 32 * qq], sq4[lane + 32 * qq]);
        s = warp_sum(s);
        if (lane == 0) {
            if (MASK && (S < len) && (l >= len)) s = -INFINITY;
            sc[l] = s;
        }
    }
    __syncthreads();

    float v = (t < S) ? sc[t] : -INFINITY;
    sred[t] = v; __syncthreads();
    #pragma unroll
    for (int o = 256; o > 0; o >>= 1) { if (t < o) sred[t] = fmaxf(sred[t], sred[t + o]); __syncthreads(); }
    float m = sred[0]; __syncthreads();
    float e = (t < S) ? expf(sc[t] - m) : 0.f;
    sred[t] = e; __syncthreads();
    #pragma unroll
    for (int o = 256; o > 0; o >>= 1) { if (t < o) sred[t] += sred[t + o]; __syncthreads(); }
    float ssum = sred[0]; __syncthreads();
    if (t < S) {
        float a = e / ssum;
        sc[t] = a;
        if (STORE_ALPHA) g_alpha[b * S + t] = a;
    }
    __syncthreads();

    float c = 0.f;
    const float* base = kv + (size_t)b * HSZ + t;
    #pragma unroll 8
    for (int l = 0; l < S; l++) c += sc[l] * base[(size_t)l * BSZ * HSZ];
    g_nh[b * K3H + NHOFF + t] = c;
}

// ---------------- K4: pointer prob (block per b) --------------------------------
__global__ void __launch_bounds__(256) k_pointer(
    const float* __restrict__ W_ptr, const float* __restrict__ b_ptr)
{
    __shared__ float sred[8];
    const int b = blockIdx.x;
    const int t = threadIdx.x;
    const int w = t >> 5, lane = t & 31;
    float s = 0.f;
    #pragma unroll
    for (int i = t; i < K3H; i += 256) s += g_nh[b * K3H + i] * W_ptr[i];
    s = warp_sum(s);
    if (lane == 0) sred[w] = s;
    __syncthreads();
    if (t == 0) {
        float tot = 0.f;
        #pragma unroll
        for (int i = 0; i < 8; i++) tot += sred[i];
        g_p[b] = tot + b_ptr[0];
    }
}

// ---------------- K5: bf16 mma.sync GEMM (R11 config) ---------------------------
#define GBN 128
#define GBK 32
#define NKT (K3H / GBK)     // 48
#define AST 20              // row stride in words; conflict-free frag pattern
#define TBUF (BSZ * AST)

__device__ __forceinline__ void mma_bf16(float* d, const uint32_t* a, const uint32_t* b) {
    asm volatile(
        "mma.sync.aligned.m16n8k16.row.col.f32.bf16.bf16.f32 "
        "{%0,%1,%2,%3}, {%4,%5,%6,%7}, {%8,%9}, {%0,%1,%2,%3};\n"
        : "+f"(d[0]), "+f"(d[1]), "+f"(d[2]), "+f"(d[3])
        : "r"(a[0]), "r"(a[1]), "r"(a[2]), "r"(a[3]), "r"(b[0]), "r"(b[1]));
}

__global__ void __launch_bounds__(256) k_gemm_bf16(
    const float* __restrict__ W,        // (V, K3H)
    const float* __restrict__ bias,     // (V,)
    float* __restrict__ out)            // (B, V)
{
    __shared__ uint32_t sa[2][TBUF];
    __shared__ uint32_t sb[2][TBUF];

    const int tid  = threadIdx.x;
    const int warp = tid >> 5, lane = tid & 31;
    const int g    = lane >> 2, tig = lane & 3;
    const int wm   = (warp >> 2) * 64;
    const int wn   = (warp & 3) * 32;
    const int n0   = blockIdx.x * GBN;

    const int srow = tid >> 1;
    const int shalf = (tid & 1);
    const bool bvalid = (n0 + srow) < VSZ;
    const float* aptr = g_nh + (size_t)srow * K3H + shalf * 16;
    const float* bptr = W + (size_t)(n0 + srow) * K3H + shalf * 16;

    uint32_t pa[8], pb[8];

    auto ldg_pack = [&](int kt) {
        const float4* a4 = (const float4*)(aptr + kt * GBK);
        #pragma unroll
        for (int q = 0; q < 4; q++) {
            float4 v = a4[q];
            __nv_bfloat162 lo = __floats2bfloat162_rn(v.x, v.y);
            __nv_bfloat162 hi = __floats2bfloat162_rn(v.z, v.w);
            pa[2 * q]     = *(uint32_t*)&lo;
            pa[2 * q + 1] = *(uint32_t*)&hi;
        }
        if (bvalid) {
            const float4* b4 = (const float4*)(bptr + kt * GBK);
            #pragma unroll
            for (int q = 0; q < 4; q++) {
                float4 v = b4[q];
                __nv_bfloat162 lo = __floats2bfloat162_rn(v.x, v.y);
                __nv_bfloat162 hi = __floats2bfloat162_rn(v.z, v.w);
                pb[2 * q]     = *(uint32_t*)&lo;
                pb[2 * q + 1] = *(uint32_t*)&hi;
            }
        } else {
            #pragma unroll
            for (int q = 0; q < 8; q++) pb[q] = 0u;
        }
    };
    auto sts = [&](int buf) {
        uint32_t* A = &sa[buf][srow * AST + shalf * 8];
        uint32_t* B = &sb[buf][srow * AST + shalf * 8];
        *(uint4*)(A)     = make_uint4(pa[0], pa[1], pa[2], pa[3]);
        *(uint4*)(A + 4) = make_uint4(pa[4], pa[5], pa[6], pa[7]);
        *(uint4*)(B)     = make_uint4(pb[0], pb[1], pb[2], pb[3]);
        *(uint4*)(B + 4) = make_uint4(pb[4], pb[5], pb[6], pb[7]);
    };

    float acc[4][4][4];
    #pragma unroll
    for (int mi = 0; mi < 4; mi++)
        #pragma unroll
        for (int nf = 0; nf < 4; nf++)
            #pragma unroll
            for (int r = 0; r < 4; r++) acc[mi][nf][r] = 0.f;

    ldg_pack(0);
    sts(0);
    __syncthreads();

    for (int t = 0; t < NKT; t++) {
        const int cur = t & 1;
        if (t + 1 < NKT) ldg_pack(t + 1);        // overlap LDG with mma

        #pragma unroll
        for (int kh = 0; kh < 2; kh++) {
            const int kb = kh * 8 + tig;
            uint32_t bf[4][2];
            #pragma unroll
            for (int nf = 0; nf < 4; nf++) {
                const int r = wn + nf * 8 + g;
                bf[nf][0] = sb[cur][r * AST + kb];
                bf[nf][1] = sb[cur][r * AST + kb + 4];
            }
            #pragma unroll
            for (int mi = 0; mi < 4; mi++) {
                const int r0 = wm + mi * 16 + g;
                uint32_t af[4];
                af[0] = sa[cur][r0 * AST + kb];
                af[1] = sa[cur][(r0 + 8) * AST + kb];
                af[2] = sa[cur][r0 * AST + kb + 4];
                af[3] = sa[cur][(r0 + 8) * AST + kb + 4];
                #pragma unroll
                for (int nf = 0; nf < 4; nf++) mma_bf16(acc[mi][nf], af, bf[nf]);
            }
        }

        if (t + 1 < NKT) {
            sts((t + 1) & 1);
            __syncthreads();
        }
    }

    #pragma unroll
    for (int mi = 0; mi < 4; mi++) {
        const int m = wm + mi * 16 + g;
        #pragma unroll
        for (int nf = 0; nf < 4; nf++) {
            const int gn = n0 + wn + nf * 8 + 2 * tig;
            if (gn < VSZ) {
                float2 bv = *(const float2*)(bias + gn);
                float2 o0 = { acc[mi][nf][0] + bv.x, acc[mi][nf][1] + bv.y };
                float2 o1 = { acc[mi][nf][2] + bv.x, acc[mi][nf][3] + bv.y };
                *(float2*)(out + (size_t)m * VSZ + gn) = o0;
                *(float2*)(out + (size_t)(m + 8) * VSZ + gn) = o1;
            }
        }
    }
}

// ---------------- K6: fused logsumexp + finalize (block per row) -----------------
__global__ void __launch_bounds__(1024) k_lsefin(float* __restrict__ out)
{
    __shared__ float sr[1024];
    const int b = blockIdx.x, t = threadIdx.x;
    float* row = out + (size_t)b * VSZ;

    float m = -INFINITY;
    for (int i = t; i < VSZ; i += 1024) m = fmaxf(m, row[i]);
    sr[t] = m; __syncthreads();
    #pragma unroll
    for (int o = 512; o > 0; o >>= 1) { if (t < o) sr[t] = fmaxf(sr[t], sr[t + o]); __syncthreads(); }
    m = sr[0]; __syncthreads();

    float s = 0.f;
    for (int i = t; i < VSZ; i += 1024) s += expf(row[i] - m);
    sr[t] = s; __syncthreads();
    #pragma unroll
    for (int o = 512; o > 0; o >>= 1) { if (t < o) sr[t] += sr[t + o]; __syncthreads(); }
    float lse = m + logf(sr[0]);
    float scale = 1.f - g_p[b];
    __syncthreads();

    for (int i = t; i < VSZ; i += 1024) row[i] = scale * (row[i] - lse);
}

// ---------------- K7: pointer scatter add --------------------------------------
__global__ void __launch_bounds__(256) k_scatter(
    float* __restrict__ out, const int* __restrict__ enc_inputs)
{
    int i = blockIdx.x * blockDim.x + threadIdx.x;
    if (i >= BSZ * LSZ) return;
    int b = i & (BSZ - 1);
    int l = i >> 7;
    int tok = enc_inputs[l * BSZ + b];
    atomicAdd(out + (size_t)b * VSZ + tok, g_p[b] * g_alpha[b * LSZ + l]);
}

// ---------------- launch --------------------------------------------------------
extern "C" void kernel_launch(void* const* d_in, const int* in_sizes, int n_in,
                              void* d_out, int out_size)
{
    const int*   inputs      = (const int*)  d_in[0];
    const float* hidden      = (const float*)d_in[1];
    const float* enc_hidden  = (const float*)d_in[2];
    const int*   enc_lengths = (const int*)  d_in[3];
    const float* prev_w      = (const float*)d_in[4];
    const float* dec_hidden  = (const float*)d_in[5];
    const int*   enc_inputs  = (const int*)  d_in[6];

    int wbase = 7;
    for (int i = 7; i < n_in; i++) {
        if (in_sizes[i] == VSZ * ESZ) { wbase = i; break; }
    }
    const float* emb   = (const float*)d_in[wbase + 0];
    const float* W_ih  = (const float*)d_in[wbase + 1];
    const float* W_hh  = (const float*)d_in[wbase + 2];
    const float* b_ih  = (const float*)d_in[wbase + 3];
    const float* b_hh  = (const float*)d_in[wbase + 4];
    const float* W_ae  = (const float*)d_in[wbase + 5];
    const float* b_ae  = (const float*)d_in[wbase + 6];
    const float* W_ad  = (const float*)d_in[wbase + 7];
    const float* b_ad  = (const float*)d_in[wbase + 8];
    const float* W_ptr = (const float*)d_in[wbase + 9];
    const float* b_ptr = (const float*)d_in[wbase + 10];
    const float* W_out = (const float*)d_in[wbase + 11];
    const float* b_out = (const float*)d_in[wbase + 12];

    float* out     = (float*)d_out;
    float* h_out   = out + (size_t)BSZ * VSZ;
    float* pw_out  = h_out + (size_t)BSZ * HSZ;

    // slot 0
    k_gru_gates<<<BSZ / 2, 256>>>(inputs, hidden, emb, W_ih, W_hh, b_ih, b_hh, h_out);
    // slot 1
    k_proj<<<BSZ / 2, 256>>>(h_out, W_ae, b_ae, W_ad, b_ad);
    // slot 2
    k_attn<TSZ, 2 * HSZ, true,  false, false><<<BSZ, 512>>>(dec_hidden, enc_lengths);
    // slot 3  <-- ncu capture lands here: encoder attention
    k_attn<LSZ, 0,       false, true,  true ><<<BSZ, 512>>>(enc_hidden, enc_lengths);
    // slot 4
    k_pointer<<<BSZ, 256>>>(W_ptr, b_ptr);
    // slot 5
    k_gemm_bf16<<<(VSZ + GBN - 1) / GBN, 256>>>(W_out, b_out, out);
    // slot 6
    k_lsefin<<<BSZ, 1024>>>(out);
    // slot 7
    k_scatter<<<(BSZ * LSZ + 255) / 256, 256>>>(out, enc_inputs);

    cudaMemcpyAsync(pw_out, prev_w, (size_t)BSZ * LSZ * sizeof(float),
                    cudaMemcpyDeviceToDevice, 0);
}

// round 16
// speedup vs baseline: 1.3801x; 1.0246x over previous
#include <cuda_runtime.h>
#include <cuda_bf16.h>
#include <math.h>
#include <stdint.h>

#define VSZ 50000
#define ESZ 256
#define HSZ 512
#define BSZ 128
#define LSZ 400
#define TSZ 100
#define K3H 1536

// ---------------- scratch (device globals; no allocation allowed) ----------------
__device__ float g_te[BSZ * HSZ];
__device__ float g_td[BSZ * HSZ];
__device__ float g_alpha[BSZ * LSZ];
__device__ float g_nh[BSZ * K3H];     // [c_t_e | h | c_t_d]
__device__ float g_p[BSZ];            // pointer_prob

__device__ __forceinline__ float warp_sum(float v) {
    #pragma unroll
    for (int o = 16; o > 0; o >>= 1) v += __shfl_down_sync(0xffffffffu, v, o);
    return v;
}
__device__ __forceinline__ float dot4(float4 a, float4 b) {
    return a.x * b.x + a.y * b.y + a.z * b.z + a.w * b.w;
}

// ---------------- K0: embed + GRU gates (2 batch rows per block) ------------------
__global__ void __launch_bounds__(256) k_gru_gates(
    const int* __restrict__ inputs,
    const float* __restrict__ hidden,
    const float* __restrict__ emb,
    const float* __restrict__ W_ih,
    const float* __restrict__ W_hh,
    const float* __restrict__ b_ih, const float* __restrict__ b_hh,
    float* __restrict__ h_out)
{
    __shared__ float4 sx4[2][64];
    __shared__ float4 sh4[2][128];
    __shared__ float sgi[2][K3H];
    __shared__ float sgh[2][K3H];

    const int b0 = blockIdx.x * 2;
    const int t = threadIdx.x;
    const int w = t >> 5, lane = t & 31;

    if (t < 128) {
        int u = t >> 6, q = t & 63;
        sx4[u][q] = ((const float4*)(emb + (size_t)inputs[b0 + u] * ESZ))[q];
    }
    {
        int u = t >> 7, q = t & 127;
        sh4[u][q] = ((const float4*)(hidden + (size_t)(b0 + u) * HSZ))[q];
    }
    __syncthreads();

    for (int j = w; j < K3H; j += 8) {
        const float4* wi4 = (const float4*)(W_ih + (size_t)j * ESZ);
        const float4* wh4 = (const float4*)(W_hh + (size_t)j * HSZ);
        float si0 = 0.f, si1 = 0.f, sg0 = 0.f, sg1 = 0.f;
        #pragma unroll
        for (int q = 0; q < 2; q++) {
            float4 wv = wi4[lane + 32 * q];
            si0 += dot4(wv, sx4[0][lane + 32 * q]);
            si1 += dot4(wv, sx4[1][lane + 32 * q]);
        }
        #pragma unroll
        for (int q = 0; q < 4; q++) {
            float4 wv = wh4[lane + 32 * q];
            sg0 += dot4(wv, sh4[0][lane + 32 * q]);
            sg1 += dot4(wv, sh4[1][lane + 32 * q]);
        }
        si0 = warp_sum(si0); si1 = warp_sum(si1);
        sg0 = warp_sum(sg0); sg1 = warp_sum(sg1);
        if (lane == 0) {
            float bi = b_ih[j], bh = b_hh[j];
            sgi[0][j] = si0 + bi; sgi[1][j] = si1 + bi;
            sgh[0][j] = sg0 + bh; sgh[1][j] = sg1 + bh;
        }
    }
    __syncthreads();

    const float* shf = (const float*)sh4;
    #pragma unroll
    for (int i = t; i < 2 * HSZ; i += 256) {
        int u = i >> 9, hh = i & (HSZ - 1);
        float r = 1.f / (1.f + expf(-(sgi[u][hh] + sgh[u][hh])));
        float z = 1.f / (1.f + expf(-(sgi[u][hh + HSZ] + sgh[u][hh + HSZ])));
        float n = tanhf(sgi[u][hh + 2 * HSZ] + r * sgh[u][hh + 2 * HSZ]);
        float hn = (1.f - z) * n + z * shf[u * HSZ + hh];
        h_out[(b0 + u) * HSZ + hh] = hn;
        g_nh[(b0 + u) * K3H + HSZ + hh] = hn;
    }
}

// ---------------- K1: te/td projections (2 batch rows per block) -----------------
__global__ void __launch_bounds__(256) k_proj(
    const float* __restrict__ h_in,
    const float* __restrict__ W_ae, const float* __restrict__ b_ae,
    const float* __restrict__ W_ad, const float* __restrict__ b_ad)
{
    __shared__ float4 sh4[2][128];

    const int b0 = blockIdx.x * 2;
    const int t = threadIdx.x;
    const int w = t >> 5, lane = t & 31;

    {
        int u = t >> 7, q = t & 127;
        sh4[u][q] = ((const float4*)(h_in + (size_t)(b0 + u) * HSZ))[q];
    }
    __syncthreads();

    for (int j = w; j < HSZ; j += 8) {
        const float4* wa4 = (const float4*)(W_ae + (size_t)j * HSZ);
        const float4* wd4 = (const float4*)(W_ad + (size_t)j * HSZ);
        float a0 = 0.f, a1 = 0.f, d0 = 0.f, d1 = 0.f;
        #pragma unroll
        for (int q = 0; q < 4; q++) {
            float4 h0 = sh4[0][lane + 32 * q];
            float4 h1 = sh4[1][lane + 32 * q];
            float4 av = wa4[lane + 32 * q];
            float4 dv = wd4[lane + 32 * q];
            a0 += dot4(av, h0); a1 += dot4(av, h1);
            d0 += dot4(dv, h0); d1 += dot4(dv, h1);
        }
        a0 = warp_sum(a0); a1 = warp_sum(a1);
        d0 = warp_sum(d0); d1 = warp_sum(d1);
        if (lane == 0) {
            float ba = b_ae[j], bd = b_ad[j];
            g_te[b0 * HSZ + j] = a0 + ba; g_te[(b0 + 1) * HSZ + j] = a1 + ba;
            g_td[b0 * HSZ + j] = d0 + bd; g_td[(b0 + 1) * HSZ + j] = d1 + bd;
        }
    }
}

// ---------------- K2: fused attention (blocks 0-127: encoder, 128-255: decoder) --
__global__ void __launch_bounds__(512) k_attn2(
    const float* __restrict__ enc_kv,
    const float* __restrict__ dec_kv,
    const int* __restrict__ lengths)
{
    __shared__ float4 sq4[128];
    __shared__ float sc[LSZ];
    __shared__ float sred[512];

    const bool is_enc = blockIdx.x < BSZ;
    const int b = blockIdx.x & (BSZ - 1);
    const int t = threadIdx.x;
    const int w = t >> 5, lane = t & 31;

    const int S = is_enc ? LSZ : TSZ;
    const int nhoff = is_enc ? 0 : 2 * HSZ;
    const float* kv = is_enc ? enc_kv : dec_kv;
    const float* q = is_enc ? g_te : g_td;

    if (t < 128) sq4[t] = ((const float4*)(q + (size_t)b * HSZ))[t];
    __syncthreads();

    const int len = lengths[b];
    const bool mask_on = is_enc && (LSZ < len);   // matches reference semantics

    // scores
    for (int l = w; l < S; l += 16) {
        const float4* row4 = (const float4*)(kv + ((size_t)l * BSZ + b) * HSZ);
        float s = 0.f;
        #pragma unroll
        for (int qq = 0; qq < 4; qq++)
            s += dot4(row4[lane + 32 * qq], sq4[lane + 32 * qq]);
        s = warp_sum(s);
        if (lane == 0) {
            if (mask_on && (l >= len)) s = -INFINITY;
            sc[l] = s;
        }
    }
    __syncthreads();

    // softmax over S
    float v = (t < S) ? sc[t] : -INFINITY;
    sred[t] = v; __syncthreads();
    #pragma unroll
    for (int o = 256; o > 0; o >>= 1) { if (t < o) sred[t] = fmaxf(sred[t], sred[t + o]); __syncthreads(); }
    float m = sred[0]; __syncthreads();
    float e = (t < S) ? expf(sc[t] - m) : 0.f;
    sred[t] = e; __syncthreads();
    #pragma unroll
    for (int o = 256; o > 0; o >>= 1) { if (t < o) sred[t] += sred[t + o]; __syncthreads(); }
    float ssum = sred[0]; __syncthreads();
    if (t < S) {
        float a = e / ssum;
        sc[t] = a;
        if (is_enc) g_alpha[b * LSZ + t] = a;
    }
    __syncthreads();

    // context
    float c = 0.f;
    const float* base = kv + (size_t)b * HSZ + t;
    #pragma unroll 8
    for (int l = 0; l < S; l++) c += sc[l] * base[(size_t)l * BSZ * HSZ];
    g_nh[b * K3H + nhoff + t] = c;
}

// ---------------- K4: pointer prob (block per b) --------------------------------
__global__ void __launch_bounds__(256) k_pointer(
    const float* __restrict__ W_ptr, const float* __restrict__ b_ptr)
{
    __shared__ float sred[8];
    const int b = blockIdx.x;
    const int t = threadIdx.x;
    const int w = t >> 5, lane = t & 31;
    float s = 0.f;
    #pragma unroll
    for (int i = t; i < K3H; i += 256) s += g_nh[b * K3H + i] * W_ptr[i];
    s = warp_sum(s);
    if (lane == 0) sred[w] = s;
    __syncthreads();
    if (t == 0) {
        float tot = 0.f;
        #pragma unroll
        for (int i = 0; i < 8; i++) tot += sred[i];
        g_p[b] = tot + b_ptr[0];
    }
}

// ---------------- K5: bf16 mma.sync GEMM (R11 config — known best) ---------------
#define GBN 128
#define GBK 32
#define NKT (K3H / GBK)     // 48
#define AST 20
#define TBUF (BSZ * AST)

__device__ __forceinline__ void mma_bf16(float* d, const uint32_t* a, const uint32_t* b) {
    asm volatile(
        "mma.sync.aligned.m16n8k16.row.col.f32.bf16.bf16.f32 "
        "{%0,%1,%2,%3}, {%4,%5,%6,%7}, {%8,%9}, {%0,%1,%2,%3};\n"
        : "+f"(d[0]), "+f"(d[1]), "+f"(d[2]), "+f"(d[3])
        : "r"(a[0]), "r"(a[1]), "r"(a[2]), "r"(a[3]), "r"(b[0]), "r"(b[1]));
}

__global__ void __launch_bounds__(256) k_gemm_bf16(
    const float* __restrict__ W,
    const float* __restrict__ bias,
    float* __restrict__ out)
{
    __shared__ uint32_t sa[2][TBUF];
    __shared__ uint32_t sb[2][TBUF];

    const int tid  = threadIdx.x;
    const int warp = tid >> 5, lane = tid & 31;
    const int g    = lane >> 2, tig = lane & 3;
    const int wm   = (warp >> 2) * 64;
    const int wn   = (warp & 3) * 32;
    const int n0   = blockIdx.x * GBN;

    const int srow = tid >> 1;
    const int shalf = (tid & 1);
    const bool bvalid = (n0 + srow) < VSZ;
    const float* aptr = g_nh + (size_t)srow * K3H + shalf * 16;
    const float* bptr = W + (size_t)(n0 + srow) * K3H + shalf * 16;

    uint32_t pa[8], pb[8];

    auto ldg_pack = [&](int kt) {
        const float4* a4 = (const float4*)(aptr + kt * GBK);
        #pragma unroll
        for (int q = 0; q < 4; q++) {
            float4 v = a4[q];
            __nv_bfloat162 lo = __floats2bfloat162_rn(v.x, v.y);
            __nv_bfloat162 hi = __floats2bfloat162_rn(v.z, v.w);
            pa[2 * q]     = *(uint32_t*)&lo;
            pa[2 * q + 1] = *(uint32_t*)&hi;
        }
        if (bvalid) {
            const float4* b4 = (const float4*)(bptr + kt * GBK);
            #pragma unroll
            for (int q = 0; q < 4; q++) {
                float4 v = b4[q];
                __nv_bfloat162 lo = __floats2bfloat162_rn(v.x, v.y);
                __nv_bfloat162 hi = __floats2bfloat162_rn(v.z, v.w);
                pb[2 * q]     = *(uint32_t*)&lo;
                pb[2 * q + 1] = *(uint32_t*)&hi;
            }
        } else {
            #pragma unroll
            for (int q = 0; q < 8; q++) pb[q] = 0u;
        }
    };
    auto sts = [&](int buf) {
        uint32_t* A = &sa[buf][srow * AST + shalf * 8];
        uint32_t* B = &sb[buf][srow * AST + shalf * 8];
        *(uint4*)(A)     = make_uint4(pa[0], pa[1], pa[2], pa[3]);
        *(uint4*)(A + 4) = make_uint4(pa[4], pa[5], pa[6], pa[7]);
        *(uint4*)(B)     = make_uint4(pb[0], pb[1], pb[2], pb[3]);
        *(uint4*)(B + 4) = make_uint4(pb[4], pb[5], pb[6], pb[7]);
    };

    float acc[4][4][4];
    #pragma unroll
    for (int mi = 0; mi < 4; mi++)
        #pragma unroll
        for (int nf = 0; nf < 4; nf++)
            #pragma unroll
            for (int r = 0; r < 4; r++) acc[mi][nf][r] = 0.f;

    ldg_pack(0);
    sts(0);
    __syncthreads();

    for (int t = 0; t < NKT; t++) {
        const int cur = t & 1;
        if (t + 1 < NKT) ldg_pack(t + 1);

        #pragma unroll
        for (int kh = 0; kh < 2; kh++) {
            const int kb = kh * 8 + tig;
            uint32_t bf[4][2];
            #pragma unroll
            for (int nf = 0; nf < 4; nf++) {
                const int r = wn + nf * 8 + g;
                bf[nf][0] = sb[cur][r * AST + kb];
                bf[nf][1] = sb[cur][r * AST + kb + 4];
            }
            #pragma unroll
            for (int mi = 0; mi < 4; mi++) {
                const int r0 = wm + mi * 16 + g;
                uint32_t af[4];
                af[0] = sa[cur][r0 * AST + kb];
                af[1] = sa[cur][(r0 + 8) * AST + kb];
                af[2] = sa[cur][r0 * AST + kb + 4];
                af[3] = sa[cur][(r0 + 8) * AST + kb + 4];
                #pragma unroll
                for (int nf = 0; nf < 4; nf++) mma_bf16(acc[mi][nf], af, bf[nf]);
            }
        }

        if (t + 1 < NKT) {
            sts((t + 1) & 1);
            __syncthreads();
        }
    }

    #pragma unroll
    for (int mi = 0; mi < 4; mi++) {
        const int m = wm + mi * 16 + g;
        #pragma unroll
        for (int nf = 0; nf < 4; nf++) {
            const int gn = n0 + wn + nf * 8 + 2 * tig;
            if (gn < VSZ) {
                float2 bv = *(const float2*)(bias + gn);
                float2 o0 = { acc[mi][nf][0] + bv.x, acc[mi][nf][1] + bv.y };
                float2 o1 = { acc[mi][nf][2] + bv.x, acc[mi][nf][3] + bv.y };
                *(float2*)(out + (size_t)m * VSZ + gn) = o0;
                *(float2*)(out + (size_t)(m + 8) * VSZ + gn) = o1;
            }
        }
    }
}

// ---------------- K6: fused online logsumexp + finalize (block per row) ----------
__global__ void __launch_bounds__(1024) k_lsefin(float* __restrict__ out)
{
    __shared__ float srm[1024];
    __shared__ float srs[1024];
    const int b = blockIdx.x, t = threadIdx.x;
    float* row = out + (size_t)b * VSZ;
    float4* row4 = (float4*)row;
    const int N4 = VSZ / 4;           // 12500

    // online max+sum in ONE read pass
    float m = -INFINITY, s = 0.f;
    for (int i = t; i < N4; i += 1024) {
        float4 v = row4[i];
        float vm = fmaxf(fmaxf(v.x, v.y), fmaxf(v.z, v.w));
        if (vm > m) { s *= expf(m - vm); m = vm; }
        s += expf(v.x - m) + expf(v.y - m) + expf(v.z - m) + expf(v.w - m);
    }
    srm[t] = m; srs[t] = s; __syncthreads();
    #pragma unroll
    for (int o = 512; o > 0; o >>= 1) {
        if (t < o) {
            float m2 = srm[t + o], s2 = srs[t + o];
            float M = fmaxf(srm[t], m2);
            srs[t] = srs[t] * expf(srm[t] - M) + s2 * expf(m2 - M);
            srm[t] = M;
        }
        __syncthreads();
    }
    float lse = srm[0] + logf(srs[0]);
    float scale = 1.f - g_p[b];
    __syncthreads();

    for (int i = t; i < N4; i += 1024) {
        float4 v = row4[i];
        v.x = scale * (v.x - lse); v.y = scale * (v.y - lse);
        v.z = scale * (v.z - lse); v.w = scale * (v.w - lse);
        row4[i] = v;
    }
}

// ---------------- K7: pointer scatter add --------------------------------------
__global__ void __launch_bounds__(256) k_scatter(
    float* __restrict__ out, const int* __restrict__ enc_inputs)
{
    int i = blockIdx.x * blockDim.x + threadIdx.x;
    if (i >= BSZ * LSZ) return;
    int b = i & (BSZ - 1);
    int l = i >> 7;
    int tok = enc_inputs[l * BSZ + b];
    atomicAdd(out + (size_t)b * VSZ + tok, g_p[b] * g_alpha[b * LSZ + l]);
}

// ---------------- launch --------------------------------------------------------
extern "C" void kernel_launch(void* const* d_in, const int* in_sizes, int n_in,
                              void* d_out, int out_size)
{
    const int*   inputs      = (const int*)  d_in[0];
    const float* hidden      = (const float*)d_in[1];
    const float* enc_hidden  = (const float*)d_in[2];
    const int*   enc_lengths = (const int*)  d_in[3];
    const float* prev_w      = (const float*)d_in[4];
    const float* dec_hidden  = (const float*)d_in[5];
    const int*   enc_inputs  = (const int*)  d_in[6];

    int wbase = 7;
    for (int i = 7; i < n_in; i++) {
        if (in_sizes[i] == VSZ * ESZ) { wbase = i; break; }
    }
    const float* emb   = (const float*)d_in[wbase + 0];
    const float* W_ih  = (const float*)d_in[wbase + 1];
    const float* W_hh  = (const float*)d_in[wbase + 2];
    const float* b_ih  = (const float*)d_in[wbase + 3];
    const float* b_hh  = (const float*)d_in[wbase + 4];
    const float* W_ae  = (const float*)d_in[wbase + 5];
    const float* b_ae  = (const float*)d_in[wbase + 6];
    const float* W_ad  = (const float*)d_in[wbase + 7];
    const float* b_ad  = (const float*)d_in[wbase + 8];
    const float* W_ptr = (const float*)d_in[wbase + 9];
    const float* b_ptr = (const float*)d_in[wbase + 10];
    const float* W_out = (const float*)d_in[wbase + 11];
    const float* b_out = (const float*)d_in[wbase + 12];

    float* out     = (float*)d_out;
    float* h_out   = out + (size_t)BSZ * VSZ;
    float* pw_out  = h_out + (size_t)BSZ * HSZ;

    // slot 0
    k_gru_gates<<<BSZ / 2, 256>>>(inputs, hidden, emb, W_ih, W_hh, b_ih, b_hh, h_out);
    // slot 1
    k_proj<<<BSZ / 2, 256>>>(h_out, W_ae, b_ae, W_ad, b_ad);
    // slot 2: both attentions fused (encoder blocks + decoder blocks concurrent)
    k_attn2<<<2 * BSZ, 512>>>(enc_hidden, dec_hidden, enc_lengths);
    // slot 3  <-- profiler slot: the GEMM
    k_gemm_bf16<<<(VSZ + GBN - 1) / GBN, 256>>>(W_out, b_out, out);
    // slot 4
    k_pointer<<<BSZ, 256>>>(W_ptr, b_ptr);
    // slot 5
    k_lsefin<<<BSZ, 1024>>>(out);
    // slot 6
    k_scatter<<<(BSZ * LSZ + 255) / 256, 256>>>(out, enc_inputs);

    cudaMemcpyAsync(pw_out, prev_w, (size_t)BSZ * LSZ * sizeof(float),
                    cudaMemcpyDeviceToDevice, 0);
}